// round 15
// baseline (speedup 1.0000x reference)
#include <cuda_runtime.h>
#include <cuda_bf16.h>
#include <cuda_fp16.h>
#include <cstdint>

#define N_NODES 100000
#define N_EDGES_MAX 1600000
#define D 512

// Static device scratch
__device__ __half g_hp16[(size_t)N_NODES * D];  // projected features fp16 (102.4 MB)
__device__ __half g_wf16[D * D];                // W fp16, transposed [n][k] (0.5 MB)
__device__ int   g_cur[N_NODES];
__device__ int   g_off[N_NODES];
__device__ int2  g_edge[N_EDGES_MAX];

// ---------------------------------------------------------------------------
// fp16 mma m16n8k16 (fp32 accumulate)
// ---------------------------------------------------------------------------
__device__ __forceinline__ void mma_f16(float c[4], const uint32_t a[4], const uint32_t b[2])
{
    asm volatile(
        "mma.sync.aligned.m16n8k16.row.col.f32.f16.f16.f32 "
        "{%0,%1,%2,%3}, {%4,%5,%6,%7}, {%8,%9}, {%0,%1,%2,%3};"
        : "+f"(c[0]), "+f"(c[1]), "+f"(c[2]), "+f"(c[3])
        : "r"(a[0]), "r"(a[1]), "r"(a[2]), "r"(a[3]), "r"(b[0]), "r"(b[1]));
}

__device__ __forceinline__ uint32_t pack_h2(float x, float y)
{
    __half2 h = __floats2half2_rn(x, y);
    return reinterpret_cast<uint32_t&>(h);
}

#define CP_ASYNC16(dst_smem_u32, src_ptr) \
    asm volatile("cp.async.cg.shared.global [%0], [%1], 16;" \
                 :: "r"(dst_smem_u32), "l"(src_ptr))
#define CP_ASYNC_COMMIT() asm volatile("cp.async.commit_group;")
#define CP_ASYNC_WAIT0()  asm volatile("cp.async.wait_group 0;" ::: "memory")
#define CP_ASYNC_WAIT1()  asm volatile("cp.async.wait_group 1;" ::: "memory")

#define AS_STRIDE 40
#define BS_STRIDE 20
#define AS_STAGE  (128 * AS_STRIDE)
#define BS_STAGE  (128 * BS_STRIDE)
#define SMEM_GEMM_BYTES (3 * (AS_STAGE + BS_STAGE) * 4)   // 92160

// ---------------------------------------------------------------------------
// Kernel 0: W -> fp16, transposed [n][k]
// ---------------------------------------------------------------------------
__global__ __launch_bounds__(256) void convert_w_kernel(const float* __restrict__ w)
{
    int i = blockIdx.x * blockDim.x + threadIdx.x;   // i = n*512 + k
    if (i >= D * D) return;
    int n = i >> 9;
    int k = i & 511;
    g_wf16[i] = __float2half_rn(w[(size_t)k * D + n]);
}

// ---------------------------------------------------------------------------
// Kernel 1: FP16 GEMM, one 128-col n-chunk per launch.
// BM=128, BN=128, BK=32; warp tile 32x64; 3-stage cp.async; 2 CTAs/SM.
// ---------------------------------------------------------------------------
__global__ __launch_bounds__(256, 2) void gemm_f16_kernel(
    const float* __restrict__ h,
    const __half* __restrict__ wf,    // [n][k]
    int M,
    int n0)
{
    extern __shared__ char smem_raw[];
    float*    Asm = reinterpret_cast<float*>(smem_raw);
    uint32_t* Bsm = reinterpret_cast<uint32_t*>(smem_raw + 3 * AS_STAGE * 4);

    const int tid  = threadIdx.x;
    const int wid  = tid >> 5;
    const int lane = tid & 31;
    const int gid  = lane >> 2;
    const int tig  = lane & 3;

    const int warp_m = wid & 3;
    const int warp_n = wid >> 2;

    const int m0 = blockIdx.x * 128;

    auto load_tile = [&](int stage, int kt) {
        const int kbase = kt * 32;
        float*    As = Asm + stage * AS_STAGE;
        uint32_t* Bs = Bsm + stage * BS_STAGE;
        #pragma unroll
        for (int l = 0; l < 4; l++) {
            int e = tid + l * 256;
            int row = e >> 3, chunk = e & 7;
            int gm = min(m0 + row, M - 1);
            uint32_t d = (uint32_t)__cvta_generic_to_shared(&As[row * AS_STRIDE + chunk * 4]);
            CP_ASYNC16(d, h + (size_t)gm * D + kbase + chunk * 4);
        }
        #pragma unroll
        for (int l = 0; l < 2; l++) {
            int e = tid + l * 256;
            int row = e >> 2, chunk = e & 3;
            uint32_t d = (uint32_t)__cvta_generic_to_shared(&Bs[row * BS_STRIDE + chunk * 4]);
            CP_ASYNC16(d, wf + (size_t)(n0 + row) * D + kbase + chunk * 8);
        }
        CP_ASYNC_COMMIT();
    };

    float c[2][8][4];
    #pragma unroll
    for (int mi = 0; mi < 2; mi++)
        #pragma unroll
        for (int ni = 0; ni < 8; ni++)
            #pragma unroll
            for (int r = 0; r < 4; r++) c[mi][ni][r] = 0.0f;

    const int NK = D / 32;   // 16
    load_tile(0, 0);
    load_tile(1, 1);

    #pragma unroll 1
    for (int kt = 0; kt < NK; kt++) {
        const int s = kt % 3;
        if (kt == NK - 1) { CP_ASYNC_WAIT0(); } else { CP_ASYNC_WAIT1(); }
        __syncthreads();
        if (kt + 2 < NK) load_tile((kt + 2) % 3, kt + 2);

        const float*    As = Asm + s * AS_STAGE;
        const uint32_t* Bs = Bsm + s * BS_STAGE;

        #pragma unroll
        for (int ks = 0; ks < 2; ks++) {
            const int kf = ks * 16;

            uint32_t a[2][4];
            #pragma unroll
            for (int mi = 0; mi < 2; mi++) {
                const int mb = warp_m * 32 + mi * 16;
                float2 f0 = *reinterpret_cast<const float2*>(&As[(mb + gid    ) * AS_STRIDE + kf + 2 * tig    ]);
                float2 f1 = *reinterpret_cast<const float2*>(&As[(mb + gid + 8) * AS_STRIDE + kf + 2 * tig    ]);
                float2 f2 = *reinterpret_cast<const float2*>(&As[(mb + gid    ) * AS_STRIDE + kf + 2 * tig + 8]);
                float2 f3 = *reinterpret_cast<const float2*>(&As[(mb + gid + 8) * AS_STRIDE + kf + 2 * tig + 8]);
                a[mi][0] = pack_h2(f0.x, f0.y);
                a[mi][1] = pack_h2(f1.x, f1.y);
                a[mi][2] = pack_h2(f2.x, f2.y);
                a[mi][3] = pack_h2(f3.x, f3.y);
            }
            uint32_t b[8][2];
            #pragma unroll
            for (int ni = 0; ni < 8; ni++) {
                const int cb = warp_n * 64 + ni * 8 + gid;
                b[ni][0] = Bs[cb * BS_STRIDE + 8 * ks + tig    ];
                b[ni][1] = Bs[cb * BS_STRIDE + 8 * ks + tig + 4];
            }

            #pragma unroll
            for (int mi = 0; mi < 2; mi++)
                #pragma unroll
                for (int ni = 0; ni < 8; ni++)
                    mma_f16(c[mi][ni], a[mi], b[ni]);
        }
        __syncthreads();
    }

    #pragma unroll
    for (int mi = 0; mi < 2; mi++) {
        #pragma unroll
        for (int ni = 0; ni < 8; ni++) {
            const int mrow = m0 + warp_m * 32 + mi * 16 + gid;
            const int ncol = n0 + warp_n * 64 + ni * 8 + tig * 2;
            if (mrow < M) {
                __half2 v = __floats2half2_rn(c[mi][ni][0], c[mi][ni][1]);
                *reinterpret_cast<__half2*>(&g_hp16[(size_t)mrow * D + ncol]) = v;
            }
            if (mrow + 8 < M) {
                __half2 v = __floats2half2_rn(c[mi][ni][2], c[mi][ni][3]);
                *reinterpret_cast<__half2*>(&g_hp16[(size_t)(mrow + 8) * D + ncol]) = v;
            }
        }
    }
}

// ---------------------------------------------------------------------------
// CSR build kernels
// ---------------------------------------------------------------------------
__global__ __launch_bounds__(256) void hist_kernel(const int* __restrict__ dst, int E)
{
    int i = blockIdx.x * blockDim.x + threadIdx.x;
    int stride = gridDim.x * blockDim.x;
    for (; i < E; i += stride)
        atomicAdd(&g_cur[dst[i]], 1);
}

__global__ __launch_bounds__(1024) void scan_kernel(int N)
{
    __shared__ int wsum[32];
    __shared__ int carry_s;
    const int t = threadIdx.x, lane = t & 31, wrp = t >> 5;
    if (t == 0) carry_s = 0;
    __syncthreads();

    const int N4 = N >> 2;
    for (int base = 0; base < N4; base += 1024) {
        int i = base + t;
        int4 v = (i < N4) ? reinterpret_cast<const int4*>(g_cur)[i]
                          : make_int4(0, 0, 0, 0);
        int s = v.x + v.y + v.z + v.w;

        int x = s;
        #pragma unroll
        for (int sh = 1; sh < 32; sh <<= 1) {
            int u = __shfl_up_sync(0xFFFFFFFFu, x, sh);
            if (lane >= sh) x += u;
        }
        if (lane == 31) wsum[wrp] = x;
        __syncthreads();

        if (wrp == 0) {
            int y = wsum[lane];
            #pragma unroll
            for (int sh = 1; sh < 32; sh <<= 1) {
                int u = __shfl_up_sync(0xFFFFFFFFu, y, sh);
                if (lane >= sh) y += u;
            }
            wsum[lane] = y;
        }
        __syncthreads();

        int excl = x - s + ((wrp == 0) ? 0 : wsum[wrp - 1]) + carry_s;
        if (i < N4) {
            int4 o;
            o.x = excl;
            o.y = o.x + v.x;
            o.z = o.y + v.y;
            o.w = o.z + v.z;
            reinterpret_cast<int4*>(g_off)[i] = o;
            reinterpret_cast<int4*>(g_cur)[i] = o;
        }
        int total = wsum[31];
        __syncthreads();
        if (t == 0) carry_s += total;
        __syncthreads();
    }
}

__global__ __launch_bounds__(256) void bucket_kernel(
    const int* __restrict__ src,
    const int* __restrict__ dst,
    const float* __restrict__ ew,
    int E)
{
    int i = blockIdx.x * blockDim.x + threadIdx.x;
    int stride = gridDim.x * blockDim.x;
    for (; i < E; i += stride) {
        int d = dst[i];
        int p = atomicAdd(&g_cur[d], 1);
        g_edge[p] = make_int2(src[i], __float_as_int(ew[i]));
    }
}

// ---------------------------------------------------------------------------
// Kernel 4: column-chunk gather-aggregate + fused ReLU.
// One launch handles output cols [col0, col0+128). Block = 4 nodes x 32 lanes;
// lane owns 4 cols (8B fp16 per edge). fp32 accum, dual chains.
// ---------------------------------------------------------------------------
__global__ __launch_bounds__(128) void aggregate_chunk_kernel(
    const __half* __restrict__ hp,
    float* __restrict__ out,
    int N,
    int col0)
{
    const int grp  = threadIdx.x >> 5;           // 0..3 node-in-block
    const int lane = threadIdx.x & 31;
    const int n = blockIdx.x * 4 + grp;
    if (n >= N) return;
    const int col = col0 + lane * 4;

    int j  = g_off[n];
    const int je = g_cur[n];

    float a0[4] = {0.f,0.f,0.f,0.f};
    float a1[4] = {0.f,0.f,0.f,0.f};

    for (; j + 1 < je; j += 2) {
        int2 e0 = __ldg(&g_edge[j]);
        int2 e1 = __ldg(&g_edge[j + 1]);
        float w0 = __int_as_float(e0.y);
        float w1 = __int_as_float(e1.y);
        uint2 p0 = *reinterpret_cast<const uint2*>(hp + (size_t)e0.x * D + col);
        uint2 p1 = *reinterpret_cast<const uint2*>(hp + (size_t)e1.x * D + col);

        float2 f;
        f = __half22float2(*reinterpret_cast<__half2*>(&p0.x)); a0[0] += w0*f.x; a0[1] += w0*f.y;
        f = __half22float2(*reinterpret_cast<__half2*>(&p0.y)); a0[2] += w0*f.x; a0[3] += w0*f.y;
        f = __half22float2(*reinterpret_cast<__half2*>(&p1.x)); a1[0] += w1*f.x; a1[1] += w1*f.y;
        f = __half22float2(*reinterpret_cast<__half2*>(&p1.y)); a1[2] += w1*f.x; a1[3] += w1*f.y;
    }
    if (j < je) {
        int2 e0 = __ldg(&g_edge[j]);
        float w0 = __int_as_float(e0.y);
        uint2 p0 = *reinterpret_cast<const uint2*>(hp + (size_t)e0.x * D + col);
        float2 f;
        f = __half22float2(*reinterpret_cast<__half2*>(&p0.x)); a0[0] += w0*f.x; a0[1] += w0*f.y;
        f = __half22float2(*reinterpret_cast<__half2*>(&p0.y)); a0[2] += w0*f.x; a0[3] += w0*f.y;
    }

    float4 r;
    r.x = fmaxf(a0[0] + a1[0], 0.f);
    r.y = fmaxf(a0[1] + a1[1], 0.f);
    r.z = fmaxf(a0[2] + a1[2], 0.f);
    r.w = fmaxf(a0[3] + a1[3], 0.f);
    *reinterpret_cast<float4*>(out + (size_t)n * D + col) = r;
}

// ---------------------------------------------------------------------------
// Launch — chunked GEMM/aggregate pipeline across two streams.
// ---------------------------------------------------------------------------
extern "C" void kernel_launch(void* const* d_in, const int* in_sizes, int n_in,
                              void* d_out, int out_size)
{
    const float* h   = (const float*)d_in[0];
    const float* w   = (const float*)d_in[1];
    const float* ew  = (const float*)d_in[2];
    const int*   sv  = (const int*)d_in[3];
    const int*   dv  = (const int*)d_in[4];
    float* out       = (float*)d_out;

    const int M = in_sizes[0] / D;      // 100000
    const int E = in_sizes[2];          // 1600000

    static __half* hp  = nullptr;
    static __half* wf  = nullptr;
    static int*    cur = nullptr;
    static cudaStream_t s2 = nullptr;
    static cudaEvent_t ev_fork = nullptr, ev_join = nullptr;
    static cudaEvent_t evG[4] = {nullptr, nullptr, nullptr, nullptr};
    static bool attr_set = false;
    if (!hp)  cudaGetSymbolAddress((void**)&hp,  g_hp16);
    if (!wf)  cudaGetSymbolAddress((void**)&wf,  g_wf16);
    if (!cur) cudaGetSymbolAddress((void**)&cur, g_cur);
    if (!s2) {
        cudaStreamCreateWithFlags(&s2, cudaStreamNonBlocking);
        cudaEventCreateWithFlags(&ev_fork, cudaEventDisableTiming);
        cudaEventCreateWithFlags(&ev_join, cudaEventDisableTiming);
        for (int c = 0; c < 4; c++)
            cudaEventCreateWithFlags(&evG[c], cudaEventDisableTiming);
    }
    if (!attr_set) {
        cudaFuncSetAttribute(gemm_f16_kernel,
                             cudaFuncAttributeMaxDynamicSharedMemorySize, SMEM_GEMM_BYTES);
        attr_set = true;
    }

    // Fork
    cudaEventRecord(ev_fork, 0);
    cudaStreamWaitEvent(s2, ev_fork, 0);

    // Branch B (side): CSR build
    cudaMemsetAsync(cur, 0, (size_t)M * sizeof(int), s2);
    int eblocks = min((E + 255) / 256, 148 * 8);
    hist_kernel<<<eblocks, 256, 0, s2>>>(dv, E);
    scan_kernel<<<1, 1024, 0, s2>>>(M);
    bucket_kernel<<<eblocks, 256, 0, s2>>>(sv, dv, ew, E);

    // Branch A (main): W conversion, then 4 GEMM n-chunks (each records event)
    convert_w_kernel<<<(D * D + 255) / 256, 256>>>(w);
    dim3 ggrid((M + 127) / 128, 1);
    for (int c = 0; c < 4; c++) {
        gemm_f16_kernel<<<ggrid, 256, SMEM_GEMM_BYTES>>>(h, wf, M, c * 128);
        cudaEventRecord(evG[c], 0);
    }

    // Side stream: aggregate chunk c once GEMM chunk c is done (CSR already
    // ordered earlier on s2)
    int ablocks = (M + 3) / 4;
    for (int c = 0; c < 4; c++) {
        cudaStreamWaitEvent(s2, evG[c], 0);
        aggregate_chunk_kernel<<<ablocks, 128, 0, s2>>>(hp, out, M, c * 128);
    }

    // Join
    cudaEventRecord(ev_join, s2);
    cudaStreamWaitEvent(0, ev_join, 0);
}

// round 16
// speedup vs baseline: 1.0305x; 1.0305x over previous
#include <cuda_runtime.h>
#include <cuda_bf16.h>
#include <cuda_fp16.h>
#include <cstdint>

#define N_NODES 100000
#define N_EDGES_MAX 1600000
#define D 512

// Static device scratch
__device__ __half g_hp16[(size_t)N_NODES * D];  // projected features fp16 (102.4 MB)
__device__ __half g_wf16[D * D];                // W fp16, transposed [n][k] (0.5 MB)
__device__ int   g_cur[N_NODES];
__device__ int   g_off[N_NODES];
__device__ int2  g_edge[N_EDGES_MAX];

// ---------------------------------------------------------------------------
// fp16 mma m16n8k16 (fp32 accumulate)
// ---------------------------------------------------------------------------
__device__ __forceinline__ void mma_f16(float c[4], const uint32_t a[4], const uint32_t b[2])
{
    asm volatile(
        "mma.sync.aligned.m16n8k16.row.col.f32.f16.f16.f32 "
        "{%0,%1,%2,%3}, {%4,%5,%6,%7}, {%8,%9}, {%0,%1,%2,%3};"
        : "+f"(c[0]), "+f"(c[1]), "+f"(c[2]), "+f"(c[3])
        : "r"(a[0]), "r"(a[1]), "r"(a[2]), "r"(a[3]), "r"(b[0]), "r"(b[1]));
}

__device__ __forceinline__ uint32_t pack_h2(float x, float y)
{
    __half2 h = __floats2half2_rn(x, y);
    return reinterpret_cast<uint32_t&>(h);
}

#define CP_ASYNC16(dst_smem_u32, src_ptr) \
    asm volatile("cp.async.cg.shared.global [%0], [%1], 16;" \
                 :: "r"(dst_smem_u32), "l"(src_ptr))
#define CP_ASYNC_COMMIT() asm volatile("cp.async.commit_group;")
#define CP_ASYNC_WAIT0()  asm volatile("cp.async.wait_group 0;" ::: "memory")
#define CP_ASYNC_WAIT1()  asm volatile("cp.async.wait_group 1;" ::: "memory")

#define AS_STRIDE 40
#define BS_STRIDE 20
#define AS_STAGE  (128 * AS_STRIDE)
#define BS_STAGE  (128 * BS_STRIDE)
#define SMEM_GEMM_BYTES (3 * (AS_STAGE + BS_STAGE) * 4)   // 92160

// ---------------------------------------------------------------------------
// Kernel 0: W -> fp16, transposed [n][k]
// ---------------------------------------------------------------------------
__global__ __launch_bounds__(256) void convert_w_kernel(const float* __restrict__ w)
{
    int i = blockIdx.x * blockDim.x + threadIdx.x;   // i = n*512 + k
    if (i >= D * D) return;
    int n = i >> 9;
    int k = i & 511;
    g_wf16[i] = __float2half_rn(w[(size_t)k * D + n]);
}

// ---------------------------------------------------------------------------
// Kernel 1: single-pass FP16 GEMM  hp16[M,512] = fp16(h @ W)
// BM=128, BN=128, BK=32; warp tile 32x64; 3-stage cp.async; 2 CTAs/SM.
// Grid = (4 n-chunks, m-blocks): n varies fastest -> the 4 n-tiles sharing
// one A m-tile are schedule-adjacent -> A read hits L2 3 of 4 times.
// ---------------------------------------------------------------------------
__global__ __launch_bounds__(256, 2) void gemm_f16_kernel(
    const float* __restrict__ h,
    const __half* __restrict__ wf,    // [n][k]
    int M)
{
    extern __shared__ char smem_raw[];
    float*    Asm = reinterpret_cast<float*>(smem_raw);
    uint32_t* Bsm = reinterpret_cast<uint32_t*>(smem_raw + 3 * AS_STAGE * 4);

    const int tid  = threadIdx.x;
    const int wid  = tid >> 5;
    const int lane = tid & 31;
    const int gid  = lane >> 2;
    const int tig  = lane & 3;

    const int warp_m = wid & 3;
    const int warp_n = wid >> 2;

    const int m0 = blockIdx.y * 128;    // y = m (slow)
    const int n0 = blockIdx.x * 128;    // x = n (fast) -> L2 A reuse

    auto load_tile = [&](int stage, int kt) {
        const int kbase = kt * 32;
        float*    As = Asm + stage * AS_STAGE;
        uint32_t* Bs = Bsm + stage * BS_STAGE;
        #pragma unroll
        for (int l = 0; l < 4; l++) {
            int e = tid + l * 256;
            int row = e >> 3, chunk = e & 7;
            int gm = min(m0 + row, M - 1);
            uint32_t d = (uint32_t)__cvta_generic_to_shared(&As[row * AS_STRIDE + chunk * 4]);
            CP_ASYNC16(d, h + (size_t)gm * D + kbase + chunk * 4);
        }
        #pragma unroll
        for (int l = 0; l < 2; l++) {
            int e = tid + l * 256;
            int row = e >> 2, chunk = e & 3;
            uint32_t d = (uint32_t)__cvta_generic_to_shared(&Bs[row * BS_STRIDE + chunk * 4]);
            CP_ASYNC16(d, wf + (size_t)(n0 + row) * D + kbase + chunk * 8);
        }
        CP_ASYNC_COMMIT();
    };

    float c[2][8][4];
    #pragma unroll
    for (int mi = 0; mi < 2; mi++)
        #pragma unroll
        for (int ni = 0; ni < 8; ni++)
            #pragma unroll
            for (int r = 0; r < 4; r++) c[mi][ni][r] = 0.0f;

    const int NK = D / 32;   // 16
    load_tile(0, 0);
    load_tile(1, 1);

    #pragma unroll 1
    for (int kt = 0; kt < NK; kt++) {
        const int s = kt % 3;
        if (kt == NK - 1) { CP_ASYNC_WAIT0(); } else { CP_ASYNC_WAIT1(); }
        __syncthreads();
        if (kt + 2 < NK) load_tile((kt + 2) % 3, kt + 2);

        const float*    As = Asm + s * AS_STAGE;
        const uint32_t* Bs = Bsm + s * BS_STAGE;

        #pragma unroll
        for (int ks = 0; ks < 2; ks++) {
            const int kf = ks * 16;

            uint32_t a[2][4];
            #pragma unroll
            for (int mi = 0; mi < 2; mi++) {
                const int mb = warp_m * 32 + mi * 16;
                float2 f0 = *reinterpret_cast<const float2*>(&As[(mb + gid    ) * AS_STRIDE + kf + 2 * tig    ]);
                float2 f1 = *reinterpret_cast<const float2*>(&As[(mb + gid + 8) * AS_STRIDE + kf + 2 * tig    ]);
                float2 f2 = *reinterpret_cast<const float2*>(&As[(mb + gid    ) * AS_STRIDE + kf + 2 * tig + 8]);
                float2 f3 = *reinterpret_cast<const float2*>(&As[(mb + gid + 8) * AS_STRIDE + kf + 2 * tig + 8]);
                a[mi][0] = pack_h2(f0.x, f0.y);
                a[mi][1] = pack_h2(f1.x, f1.y);
                a[mi][2] = pack_h2(f2.x, f2.y);
                a[mi][3] = pack_h2(f3.x, f3.y);
            }
            uint32_t b[8][2];
            #pragma unroll
            for (int ni = 0; ni < 8; ni++) {
                const int cb = warp_n * 64 + ni * 8 + gid;
                b[ni][0] = Bs[cb * BS_STRIDE + 8 * ks + tig    ];
                b[ni][1] = Bs[cb * BS_STRIDE + 8 * ks + tig + 4];
            }

            #pragma unroll
            for (int mi = 0; mi < 2; mi++)
                #pragma unroll
                for (int ni = 0; ni < 8; ni++)
                    mma_f16(c[mi][ni], a[mi], b[ni]);
        }
        __syncthreads();
    }

    #pragma unroll
    for (int mi = 0; mi < 2; mi++) {
        #pragma unroll
        for (int ni = 0; ni < 8; ni++) {
            const int mrow = m0 + warp_m * 32 + mi * 16 + gid;
            const int ncol = n0 + warp_n * 64 + ni * 8 + tig * 2;
            if (mrow < M) {
                __half2 v = __floats2half2_rn(c[mi][ni][0], c[mi][ni][1]);
                *reinterpret_cast<__half2*>(&g_hp16[(size_t)mrow * D + ncol]) = v;
            }
            if (mrow + 8 < M) {
                __half2 v = __floats2half2_rn(c[mi][ni][2], c[mi][ni][3]);
                *reinterpret_cast<__half2*>(&g_hp16[(size_t)(mrow + 8) * D + ncol]) = v;
            }
        }
    }
}

// ---------------------------------------------------------------------------
// CSR build kernels
// ---------------------------------------------------------------------------
__global__ __launch_bounds__(256) void hist_kernel(const int* __restrict__ dst, int E)
{
    int i = blockIdx.x * blockDim.x + threadIdx.x;
    int stride = gridDim.x * blockDim.x;
    for (; i < E; i += stride)
        atomicAdd(&g_cur[dst[i]], 1);
}

__global__ __launch_bounds__(1024) void scan_kernel(int N)
{
    __shared__ int wsum[32];
    __shared__ int carry_s;
    const int t = threadIdx.x, lane = t & 31, wrp = t >> 5;
    if (t == 0) carry_s = 0;
    __syncthreads();

    const int N4 = N >> 2;
    for (int base = 0; base < N4; base += 1024) {
        int i = base + t;
        int4 v = (i < N4) ? reinterpret_cast<const int4*>(g_cur)[i]
                          : make_int4(0, 0, 0, 0);
        int s = v.x + v.y + v.z + v.w;

        int x = s;
        #pragma unroll
        for (int sh = 1; sh < 32; sh <<= 1) {
            int u = __shfl_up_sync(0xFFFFFFFFu, x, sh);
            if (lane >= sh) x += u;
        }
        if (lane == 31) wsum[wrp] = x;
        __syncthreads();

        if (wrp == 0) {
            int y = wsum[lane];
            #pragma unroll
            for (int sh = 1; sh < 32; sh <<= 1) {
                int u = __shfl_up_sync(0xFFFFFFFFu, y, sh);
                if (lane >= sh) y += u;
            }
            wsum[lane] = y;
        }
        __syncthreads();

        int excl = x - s + ((wrp == 0) ? 0 : wsum[wrp - 1]) + carry_s;
        if (i < N4) {
            int4 o;
            o.x = excl;
            o.y = o.x + v.x;
            o.z = o.y + v.y;
            o.w = o.z + v.z;
            reinterpret_cast<int4*>(g_off)[i] = o;
            reinterpret_cast<int4*>(g_cur)[i] = o;
        }
        int total = wsum[31];
        __syncthreads();
        if (t == 0) carry_s += total;
        __syncthreads();
    }
}

__global__ __launch_bounds__(256) void bucket_kernel(
    const int* __restrict__ src,
    const int* __restrict__ dst,
    const float* __restrict__ ew,
    int E)
{
    int i = blockIdx.x * blockDim.x + threadIdx.x;
    int stride = gridDim.x * blockDim.x;
    for (; i < E; i += stride) {
        int d = dst[i];
        int p = atomicAdd(&g_cur[d], 1);
        g_edge[p] = make_int2(src[i], __float_as_int(ew[i]));
    }
}

// ---------------------------------------------------------------------------
// Kernel 4: per-node fp16 gather-aggregate + fused ReLU.
// 128-thread block = 2 nodes x 64 threads; thread owns 8 cols (16B per edge).
// ---------------------------------------------------------------------------
__global__ __launch_bounds__(128) void aggregate_f16_kernel(
    const __half* __restrict__ hp,
    float* __restrict__ out,
    int N)
{
    const int sub = threadIdx.x >> 6;
    const int tt  = threadIdx.x & 63;
    const int n = blockIdx.x * 2 + sub;
    if (n >= N) return;
    const int col = tt * 8;

    int j  = g_off[n];
    const int je = g_cur[n];

    float a0[8] = {0.f,0.f,0.f,0.f,0.f,0.f,0.f,0.f};
    float a1[8] = {0.f,0.f,0.f,0.f,0.f,0.f,0.f,0.f};

    for (; j + 1 < je; j += 2) {
        int2 e0 = __ldg(&g_edge[j]);
        int2 e1 = __ldg(&g_edge[j + 1]);
        float w0 = __int_as_float(e0.y);
        float w1 = __int_as_float(e1.y);
        uint4 p0 = *reinterpret_cast<const uint4*>(hp + (size_t)e0.x * D + col);
        uint4 p1 = *reinterpret_cast<const uint4*>(hp + (size_t)e1.x * D + col);

        float2 f;
        f = __half22float2(*reinterpret_cast<__half2*>(&p0.x)); a0[0] += w0*f.x; a0[1] += w0*f.y;
        f = __half22float2(*reinterpret_cast<__half2*>(&p0.y)); a0[2] += w0*f.x; a0[3] += w0*f.y;
        f = __half22float2(*reinterpret_cast<__half2*>(&p0.z)); a0[4] += w0*f.x; a0[5] += w0*f.y;
        f = __half22float2(*reinterpret_cast<__half2*>(&p0.w)); a0[6] += w0*f.x; a0[7] += w0*f.y;
        f = __half22float2(*reinterpret_cast<__half2*>(&p1.x)); a1[0] += w1*f.x; a1[1] += w1*f.y;
        f = __half22float2(*reinterpret_cast<__half2*>(&p1.y)); a1[2] += w1*f.x; a1[3] += w1*f.y;
        f = __half22float2(*reinterpret_cast<__half2*>(&p1.z)); a1[4] += w1*f.x; a1[5] += w1*f.y;
        f = __half22float2(*reinterpret_cast<__half2*>(&p1.w)); a1[6] += w1*f.x; a1[7] += w1*f.y;
    }
    if (j < je) {
        int2 e0 = __ldg(&g_edge[j]);
        float w0 = __int_as_float(e0.y);
        uint4 p0 = *reinterpret_cast<const uint4*>(hp + (size_t)e0.x * D + col);
        float2 f;
        f = __half22float2(*reinterpret_cast<__half2*>(&p0.x)); a0[0] += w0*f.x; a0[1] += w0*f.y;
        f = __half22float2(*reinterpret_cast<__half2*>(&p0.y)); a0[2] += w0*f.x; a0[3] += w0*f.y;
        f = __half22float2(*reinterpret_cast<__half2*>(&p0.z)); a0[4] += w0*f.x; a0[5] += w0*f.y;
        f = __half22float2(*reinterpret_cast<__half2*>(&p0.w)); a0[6] += w0*f.x; a0[7] += w0*f.y;
    }

    float4 r0, r1;
    r0.x = fmaxf(a0[0] + a1[0], 0.f);
    r0.y = fmaxf(a0[1] + a1[1], 0.f);
    r0.z = fmaxf(a0[2] + a1[2], 0.f);
    r0.w = fmaxf(a0[3] + a1[3], 0.f);
    r1.x = fmaxf(a0[4] + a1[4], 0.f);
    r1.y = fmaxf(a0[5] + a1[5], 0.f);
    r1.z = fmaxf(a0[6] + a1[6], 0.f);
    r1.w = fmaxf(a0[7] + a1[7], 0.f);
    *reinterpret_cast<float4*>(out + (size_t)n * D + col)     = r0;
    *reinterpret_cast<float4*>(out + (size_t)n * D + col + 4) = r1;
}

// ---------------------------------------------------------------------------
// Launch — round-14 serial two-stream structure (validated 488.6 us)
// ---------------------------------------------------------------------------
extern "C" void kernel_launch(void* const* d_in, const int* in_sizes, int n_in,
                              void* d_out, int out_size)
{
    const float* h   = (const float*)d_in[0];
    const float* w   = (const float*)d_in[1];
    const float* ew  = (const float*)d_in[2];
    const int*   sv  = (const int*)d_in[3];
    const int*   dv  = (const int*)d_in[4];
    float* out       = (float*)d_out;

    const int M = in_sizes[0] / D;      // 100000
    const int E = in_sizes[2];          // 1600000

    static __half* hp  = nullptr;
    static __half* wf  = nullptr;
    static int*    cur = nullptr;
    static cudaStream_t s2 = nullptr;
    static cudaEvent_t ev_fork = nullptr, ev_join = nullptr;
    static bool attr_set = false;
    if (!hp)  cudaGetSymbolAddress((void**)&hp,  g_hp16);
    if (!wf)  cudaGetSymbolAddress((void**)&wf,  g_wf16);
    if (!cur) cudaGetSymbolAddress((void**)&cur, g_cur);
    if (!s2) {
        cudaStreamCreateWithFlags(&s2, cudaStreamNonBlocking);
        cudaEventCreateWithFlags(&ev_fork, cudaEventDisableTiming);
        cudaEventCreateWithFlags(&ev_join, cudaEventDisableTiming);
    }
    if (!attr_set) {
        cudaFuncSetAttribute(gemm_f16_kernel,
                             cudaFuncAttributeMaxDynamicSharedMemorySize, SMEM_GEMM_BYTES);
        attr_set = true;
    }

    // Fork
    cudaEventRecord(ev_fork, 0);
    cudaStreamWaitEvent(s2, ev_fork, 0);

    // Branch A (main): W conversion -> GEMM (grid: n fast, m slow)
    convert_w_kernel<<<(D * D + 255) / 256, 256>>>(w);
    dim3 ggrid(D / 128, (M + 127) / 128);
    gemm_f16_kernel<<<ggrid, 256, SMEM_GEMM_BYTES>>>(h, wf, M);

    // Branch B (side): CSR build
    cudaMemsetAsync(cur, 0, (size_t)M * sizeof(int), s2);
    int eblocks = min((E + 255) / 256, 148 * 8);
    hist_kernel<<<eblocks, 256, 0, s2>>>(dv, E);
    scan_kernel<<<1, 1024, 0, s2>>>(M);
    bucket_kernel<<<eblocks, 256, 0, s2>>>(sv, dv, ew, E);

    // Join
    cudaEventRecord(ev_join, s2);
    cudaStreamWaitEvent(0, ev_join, 0);

    // Aggregate
    aggregate_f16_kernel<<<(M + 1) / 2, 128>>>(hp, out, M);
}